// round 4
// baseline (speedup 1.0000x reference)
#include <cuda_runtime.h>
#include <math.h>
#include <stdint.h>

#define B_SZ     2
#define L_SEQ    2048
#define D_MODEL  1024
#define D_INNER  2048
#define D_STATE  16
#define DT_RANK  64
#define NROWS    (B_SZ * L_SEQ)          // 4096
#define XDBL_W   (DT_RANK + 2 * D_STATE) // 96

// ---------------- scratch (device globals; no allocs allowed) ----------------
__device__ float g_xz  [(size_t)NROWS * 2 * D_INNER];
__device__ float g_uc  [(size_t)NROWS * D_INNER];
__device__ float g_xdbl[(size_t)NROWS * XDBL_W];
__device__ float g_dt  [(size_t)NROWS * D_INNER];
__device__ float g_y   [(size_t)NROWS * D_INNER];
__device__ float g_o   [(size_t)NROWS * D_MODEL];
// tf32-rounded copies of GEMM inputs
__device__ float g_xr [(size_t)NROWS * D_MODEL];
__device__ float g_w1 [(size_t)2 * D_INNER * D_MODEL];
__device__ float g_w3 [(size_t)XDBL_W * D_INNER];
__device__ float g_w4 [(size_t)D_INNER * DT_RANK];
__device__ float g_w6 [(size_t)D_MODEL * D_INNER];

__device__ __forceinline__ unsigned f2tf32(float f) {
    unsigned r;
    asm("cvt.rna.tf32.f32 %0, %1;" : "=r"(r) : "f"(f));
    return r;
}

__device__ __forceinline__ void mma_tf32(float c[4], unsigned a0, unsigned a1,
                                         unsigned a2, unsigned a3,
                                         unsigned b0, unsigned b1) {
    asm volatile(
        "mma.sync.aligned.m16n8k8.row.col.f32.tf32.tf32.f32 "
        "{%0,%1,%2,%3}, {%4,%5,%6,%7}, {%8,%9}, {%0,%1,%2,%3};"
        : "+f"(c[0]), "+f"(c[1]), "+f"(c[2]), "+f"(c[3])
        : "r"(a0), "r"(a1), "r"(a2), "r"(a3), "r"(b0), "r"(b1));
}

// ================= tf32 tensor-core NT GEMM (inputs pre-rounded to tf32) =====
// C[m,n] = sum_k A[m,k] * B[n,k].  Block tile 128x64xK16, 256 threads = 8 warps
// (4 m x 2 n), warp tile 32x32.  Shared layout k-permuted + row-XOR swizzled:
// element (r, k=4j+i) -> word As[r][(i ^ ((r>>1)&3))*4 + j]; frag load is one
// conflict-free LDS.128; scatter STS is conflict-free.
// MODE 0: plain   MODE 1: softplus(acc + bias[n])   RND: round output to tf32
template <int MODE, int RND>
__global__ void __launch_bounds__(256, 3)
gemm_tf32(const float* __restrict__ A, const float* __restrict__ Bm,
          float* __restrict__ C, int N, int K,
          int lda, int ldb, int ldc, const float* __restrict__ bias)
{
    __shared__ unsigned As[2][128][16];
    __shared__ unsigned Bs[2][64][16];

    const int tid    = threadIdx.x;
    const int warp   = tid >> 5;
    const int lane   = tid & 31;
    const int g      = lane >> 2;
    const int tg     = lane & 3;
    const int warp_m = warp & 3;
    const int warp_n = warp >> 2;
    const int m0     = blockIdx.y * 128;
    const int n0     = blockIdx.x * 64;

    const int rA0 = tid >> 2;
    const int rA1 = rA0 + 64;
    const int jA  = tid & 3;
    const int rB  = tid >> 2;
    const int jB  = tid & 3;
    const bool bOK = (n0 + rB) < N;

    const float* Arow0 = A  + (size_t)(m0 + rA0) * lda + 4 * jA;
    const float* Arow1 = A  + (size_t)(m0 + rA1) * lda + 4 * jA;
    const float* Brow  = bOK ? (Bm + (size_t)(n0 + rB) * ldb + 4 * jB) : nullptr;

    const int swA0 = (rA0 >> 1) & 3, swA1 = (rA1 >> 1) & 3, swB = (rB >> 1) & 3;

    float acc[2][4][4];
#pragma unroll
    for (int i = 0; i < 2; i++)
#pragma unroll
        for (int j = 0; j < 4; j++)
#pragma unroll
            for (int c = 0; c < 4; c++) acc[i][j][c] = 0.f;

    const int nk = K >> 4;

    // prologue: stage chunk 0 (raw bits: inputs are already tf32-rounded)
    float4 va0 = *(const float4*)(Arow0);
    float4 va1 = *(const float4*)(Arow1);
    float4 vb  = bOK ? *(const float4*)(Brow) : make_float4(0.f, 0.f, 0.f, 0.f);
    {
        As[0][rA0][((0 ^ swA0) << 2) + jA] = __float_as_uint(va0.x);
        As[0][rA0][((1 ^ swA0) << 2) + jA] = __float_as_uint(va0.y);
        As[0][rA0][((2 ^ swA0) << 2) + jA] = __float_as_uint(va0.z);
        As[0][rA0][((3 ^ swA0) << 2) + jA] = __float_as_uint(va0.w);
        As[0][rA1][((0 ^ swA1) << 2) + jA] = __float_as_uint(va1.x);
        As[0][rA1][((1 ^ swA1) << 2) + jA] = __float_as_uint(va1.y);
        As[0][rA1][((2 ^ swA1) << 2) + jA] = __float_as_uint(va1.z);
        As[0][rA1][((3 ^ swA1) << 2) + jA] = __float_as_uint(va1.w);
        Bs[0][rB ][((0 ^ swB ) << 2) + jB] = __float_as_uint(vb.x);
        Bs[0][rB ][((1 ^ swB ) << 2) + jB] = __float_as_uint(vb.y);
        Bs[0][rB ][((2 ^ swB ) << 2) + jB] = __float_as_uint(vb.z);
        Bs[0][rB ][((3 ^ swB ) << 2) + jB] = __float_as_uint(vb.w);
    }
    __syncthreads();

    int buf = 0;
    for (int ki = 0; ki < nk; ki++) {
        const bool hasNext = (ki + 1) < nk;
        if (hasNext) {
            const int koff = (ki + 1) << 4;
            va0 = *(const float4*)(Arow0 + koff);
            va1 = *(const float4*)(Arow1 + koff);
            vb  = bOK ? *(const float4*)(Brow + koff) : make_float4(0.f, 0.f, 0.f, 0.f);
        }

        uint4 afrag[2][2];
#pragma unroll
        for (int i = 0; i < 2; i++) {
            int r1 = warp_m * 32 + i * 16 + g;
            int r2 = r1 + 8;
            afrag[i][0] = *(const uint4*)&As[buf][r1][(tg ^ ((r1 >> 1) & 3)) << 2];
            afrag[i][1] = *(const uint4*)&As[buf][r2][(tg ^ ((r2 >> 1) & 3)) << 2];
        }
        uint4 bfrag[4];
#pragma unroll
        for (int j = 0; j < 4; j++) {
            int rn = warp_n * 32 + j * 8 + g;
            bfrag[j] = *(const uint4*)&Bs[buf][rn][(tg ^ ((rn >> 1) & 3)) << 2];
        }

#pragma unroll
        for (int i = 0; i < 2; i++) {
#pragma unroll
            for (int j = 0; j < 4; j++) {
                mma_tf32(acc[i][j], afrag[i][0].x, afrag[i][1].x,
                                    afrag[i][0].y, afrag[i][1].y,
                                    bfrag[j].x, bfrag[j].y);
                mma_tf32(acc[i][j], afrag[i][0].z, afrag[i][1].z,
                                    afrag[i][0].w, afrag[i][1].w,
                                    bfrag[j].z, bfrag[j].w);
            }
        }

        if (hasNext) {
            const int nb = buf ^ 1;
            As[nb][rA0][((0 ^ swA0) << 2) + jA] = __float_as_uint(va0.x);
            As[nb][rA0][((1 ^ swA0) << 2) + jA] = __float_as_uint(va0.y);
            As[nb][rA0][((2 ^ swA0) << 2) + jA] = __float_as_uint(va0.z);
            As[nb][rA0][((3 ^ swA0) << 2) + jA] = __float_as_uint(va0.w);
            As[nb][rA1][((0 ^ swA1) << 2) + jA] = __float_as_uint(va1.x);
            As[nb][rA1][((1 ^ swA1) << 2) + jA] = __float_as_uint(va1.y);
            As[nb][rA1][((2 ^ swA1) << 2) + jA] = __float_as_uint(va1.z);
            As[nb][rA1][((3 ^ swA1) << 2) + jA] = __float_as_uint(va1.w);
            Bs[nb][rB ][((0 ^ swB ) << 2) + jB] = __float_as_uint(vb.x);
            Bs[nb][rB ][((1 ^ swB ) << 2) + jB] = __float_as_uint(vb.y);
            Bs[nb][rB ][((2 ^ swB ) << 2) + jB] = __float_as_uint(vb.z);
            Bs[nb][rB ][((3 ^ swB ) << 2) + jB] = __float_as_uint(vb.w);
        }
        __syncthreads();
        buf ^= 1;
    }

    // epilogue
#pragma unroll
    for (int i = 0; i < 2; i++) {
        int mbase = m0 + warp_m * 32 + i * 16 + g;
#pragma unroll
        for (int j = 0; j < 4; j++) {
            int nbase = n0 + warp_n * 32 + j * 8 + 2 * tg;
#pragma unroll
            for (int c = 0; c < 4; c++) {
                int m = mbase + ((c >> 1) << 3);
                int n = nbase + (c & 1);
                if (n < N) {
                    float v = acc[i][j][c];
                    if (MODE == 1) {
                        v += bias[n];
                        v = (v > 20.f) ? v : log1pf(__expf(v));
                    }
                    if (RND) v = __uint_as_float(f2tf32(v));
                    C[(size_t)m * ldc + n] = v;
                }
            }
        }
    }
}

// ---------------- tf32 pre-round (RNA) ----------------
__global__ void __launch_bounds__(256)
round_tf32_kernel(const float* __restrict__ src, float* __restrict__ dst, int n4)
{
    int i = blockIdx.x * blockDim.x + threadIdx.x;
    if (i < n4) {
        float4 v = ((const float4*)src)[i];
        v.x = __uint_as_float(f2tf32(v.x));
        v.y = __uint_as_float(f2tf32(v.y));
        v.z = __uint_as_float(f2tf32(v.z));
        v.w = __uint_as_float(f2tf32(v.w));
        ((float4*)dst)[i] = v;
    }
}

// ---------------- depthwise causal conv (k=4) + bias + SiLU (+tf32 round) ----------------
__global__ void __launch_bounds__(256)
conv_silu_kernel(const float* __restrict__ conv_w, const float* __restrict__ conv_b)
{
    int idx = blockIdx.x * blockDim.x + threadIdx.x;
    if (idx >= NROWS * D_INNER) return;
    int d = idx & (D_INNER - 1);
    int m = idx >> 11;
    int t = m & (L_SEQ - 1);

    float acc = conv_b[d];
#pragma unroll
    for (int j = 0; j < 4; j++) {
        int tt = t - 3 + j;
        if (tt >= 0)
            acc += g_xz[(size_t)(m - 3 + j) * (2 * D_INNER) + d] * conv_w[d * 4 + j];
    }
    float s = acc / (1.f + __expf(-acc));
    g_uc[(size_t)m * D_INNER + d] = __uint_as_float(f2tf32(s));
}

// ---------------- selective scan (fused +u*D and *silu(z); rounds y) ----------------
__global__ void __launch_bounds__(128)
scan_kernel(const float* __restrict__ A_log, const float* __restrict__ Dw)
{
    const int blk = blockIdx.x;
    const int b   = blk >> 6;
    const int c0  = (blk & 63) * 32;
    const int tid = threadIdx.x;
    const int c   = c0 + (tid >> 2);
    const int g   = tid & 3;

    const float A0 = -__expf(A_log[c * D_STATE + g * 4 + 0]);
    const float A1 = -__expf(A_log[c * D_STATE + g * 4 + 1]);
    const float A2 = -__expf(A_log[c * D_STATE + g * 4 + 2]);
    const float A3 = -__expf(A_log[c * D_STATE + g * 4 + 3]);
    const float Dc = Dw[c];

    float h0 = 0.f, h1 = 0.f, h2 = 0.f, h3 = 0.f;

    const size_t rbase = (size_t)b * L_SEQ;
    const float* dt_p = g_dt   + rbase * D_INNER + c;
    const float* uc_p = g_uc   + rbase * D_INNER + c;
    const float* xd_p = g_xdbl + rbase * XDBL_W;
    const float* z_p  = g_xz   + rbase * (2 * D_INNER) + D_INNER + c;
    float*       y_p  = g_y    + rbase * D_INNER + c;

    for (int t = 0; t < L_SEQ; t++) {
        float  dtv = dt_p[(size_t)t * D_INNER];
        float  uv  = uc_p[(size_t)t * D_INNER];
        float4 Bv  = *(const float4*)(xd_p + (size_t)t * XDBL_W + DT_RANK + g * 4);
        float4 Cv  = *(const float4*)(xd_p + (size_t)t * XDBL_W + DT_RANK + D_STATE + g * 4);

        float du = dtv * uv;
        h0 = h0 * __expf(dtv * A0) + du * Bv.x;
        h1 = h1 * __expf(dtv * A1) + du * Bv.y;
        h2 = h2 * __expf(dtv * A2) + du * Bv.z;
        h3 = h3 * __expf(dtv * A3) + du * Bv.w;

        float p = h0 * Cv.x + h1 * Cv.y + h2 * Cv.z + h3 * Cv.w;
        p += __shfl_xor_sync(0xffffffffu, p, 1);
        p += __shfl_xor_sync(0xffffffffu, p, 2);

        if (g == 0) {
            float zv = z_p[(size_t)t * (2 * D_INNER)];
            float sz = zv / (1.f + __expf(-zv));
            float y  = (p + uv * Dc) * sz;
            y_p[(size_t)t * D_INNER] = __uint_as_float(f2tf32(y));
        }
    }
}

// ---------------- residual + LayerNorm ----------------
__global__ void __launch_bounds__(256)
ln_kernel(const float* __restrict__ x, const float* __restrict__ w,
          const float* __restrict__ b, float* __restrict__ out)
{
    __shared__ float red[8];
    const int m   = blockIdx.x;
    const int tid = threadIdx.x;

    float4 v  = *(const float4*)(g_o + (size_t)m * D_MODEL + tid * 4);
    float4 xr = *(const float4*)(x   + (size_t)m * D_MODEL + tid * 4);
    v.x += xr.x; v.y += xr.y; v.z += xr.z; v.w += xr.w;

    float s = v.x + v.y + v.z + v.w;
#pragma unroll
    for (int o = 16; o; o >>= 1) s += __shfl_xor_sync(0xffffffffu, s, o);
    if ((tid & 31) == 0) red[tid >> 5] = s;
    __syncthreads();
    float tot = 0.f;
#pragma unroll
    for (int i = 0; i < 8; i++) tot += red[i];
    const float mu = tot * (1.f / (float)D_MODEL);
    __syncthreads();

    float d0 = v.x - mu, d1 = v.y - mu, d2 = v.z - mu, d3 = v.w - mu;
    float sq = d0 * d0 + d1 * d1 + d2 * d2 + d3 * d3;
#pragma unroll
    for (int o = 16; o; o >>= 1) sq += __shfl_xor_sync(0xffffffffu, sq, o);
    if ((tid & 31) == 0) red[tid >> 5] = sq;
    __syncthreads();
    float tot2 = 0.f;
#pragma unroll
    for (int i = 0; i < 8; i++) tot2 += red[i];
    const float rs = rsqrtf(tot2 * (1.f / (float)D_MODEL) + 1e-5f);

    float4 wv = *(const float4*)(w + tid * 4);
    float4 bv = *(const float4*)(b + tid * 4);
    float4 o4;
    o4.x = d0 * rs * wv.x + bv.x;
    o4.y = d1 * rs * wv.y + bv.y;
    o4.z = d2 * rs * wv.z + bv.z;
    o4.w = d3 * rs * wv.w + bv.w;
    *(float4*)(out + (size_t)m * D_MODEL + tid * 4) = o4;
}

// ---------------- launch ----------------
extern "C" void kernel_launch(void* const* d_in, const int* in_sizes, int n_in,
                              void* d_out, int out_size)
{
    const float* x          = (const float*)d_in[0];
    const float* in_proj_w  = (const float*)d_in[1];
    const float* conv_w     = (const float*)d_in[2];
    const float* conv_b     = (const float*)d_in[3];
    const float* x_proj_w   = (const float*)d_in[4];
    const float* dt_proj_w  = (const float*)d_in[5];
    const float* dt_proj_b  = (const float*)d_in[6];
    const float* A_log      = (const float*)d_in[7];
    const float* Dw         = (const float*)d_in[8];
    const float* out_proj_w = (const float*)d_in[9];
    const float* ln_w       = (const float*)d_in[10];
    const float* ln_b       = (const float*)d_in[11];
    float* out = (float*)d_out;

    float *p_xz, *p_uc, *p_xdbl, *p_dt, *p_y, *p_o;
    float *p_xr, *p_w1, *p_w3, *p_w4, *p_w6;
    cudaGetSymbolAddress((void**)&p_xz,   g_xz);
    cudaGetSymbolAddress((void**)&p_uc,   g_uc);
    cudaGetSymbolAddress((void**)&p_xdbl, g_xdbl);
    cudaGetSymbolAddress((void**)&p_dt,   g_dt);
    cudaGetSymbolAddress((void**)&p_y,    g_y);
    cudaGetSymbolAddress((void**)&p_o,    g_o);
    cudaGetSymbolAddress((void**)&p_xr,   g_xr);
    cudaGetSymbolAddress((void**)&p_w1,   g_w1);
    cudaGetSymbolAddress((void**)&p_w3,   g_w3);
    cudaGetSymbolAddress((void**)&p_w4,   g_w4);
    cudaGetSymbolAddress((void**)&p_w6,   g_w6);

    // 0) pre-round all GEMM inputs to tf32 (RNA)
    round_tf32_kernel<<<(NROWS * D_MODEL / 4 + 255) / 256, 256>>>(x,          p_xr, NROWS * D_MODEL / 4);
    round_tf32_kernel<<<(2*D_INNER*D_MODEL/4 + 255) / 256, 256>>>(in_proj_w,  p_w1, 2*D_INNER*D_MODEL/4);
    round_tf32_kernel<<<(XDBL_W*D_INNER/4   + 255) / 256, 256>>>(x_proj_w,   p_w3, XDBL_W*D_INNER/4);
    round_tf32_kernel<<<(D_INNER*DT_RANK/4  + 255) / 256, 256>>>(dt_proj_w,  p_w4, D_INNER*DT_RANK/4);
    round_tf32_kernel<<<(D_MODEL*D_INNER/4  + 255) / 256, 256>>>(out_proj_w, p_w6, D_MODEL*D_INNER/4);

    // 1) xz = x @ in_proj_w.T  (4096 x 4096, K=1024)
    gemm_tf32<0, 0><<<dim3(4096 / 64, 4096 / 128), 256>>>(
        p_xr, p_w1, p_xz, 2 * D_INNER, D_MODEL, D_MODEL, D_MODEL, 2 * D_INNER, nullptr);

    // 2) u_c = silu(depthwise_conv(u) + b)   (rounded)
    conv_silu_kernel<<<(NROWS * D_INNER) / 256, 256>>>(conv_w, conv_b);

    // 3) x_dbl = u_c @ x_proj_w.T  (4096 x 96, K=2048, rounded output)
    gemm_tf32<0, 1><<<dim3(2, 4096 / 128), 256>>>(
        p_uc, p_w3, p_xdbl, XDBL_W, D_INNER, D_INNER, D_INNER, XDBL_W, nullptr);

    // 4) dt = softplus(dt_lr @ dt_proj_w.T + b)  (4096 x 2048, K=64, lda=96)
    gemm_tf32<1, 0><<<dim3(D_INNER / 64, 4096 / 128), 256>>>(
        p_xdbl, p_w4, p_dt, D_INNER, DT_RANK, XDBL_W, DT_RANK, D_INNER, dt_proj_b);

    // 5) selective scan (rounds y)
    scan_kernel<<<128, 128>>>(A_log, Dw);

    // 6) o = y @ out_proj_w.T  (4096 x 1024, K=2048)
    gemm_tf32<0, 0><<<dim3(D_MODEL / 64, 4096 / 128), 256>>>(
        p_y, p_w6, p_o, D_MODEL, D_INNER, D_INNER, D_INNER, D_MODEL, nullptr);

    // 7) out = LayerNorm(o + x)
    ln_kernel<<<NROWS, 256>>>(x, ln_w, ln_b, out);
}

// round 5
// speedup vs baseline: 1.1957x; 1.1957x over previous
#include <cuda_runtime.h>
#include <math.h>
#include <stdint.h>

#define B_SZ     2
#define L_SEQ    2048
#define D_MODEL  1024
#define D_INNER  2048
#define D_STATE  16
#define DT_RANK  64
#define NROWS    (B_SZ * L_SEQ)          // 4096
#define XDBL_W   (DT_RANK + 2 * D_STATE) // 96

// ---------------- scratch (device globals; no allocs allowed) ----------------
__device__ float g_xz  [(size_t)NROWS * 2 * D_INNER];
__device__ float g_uc  [(size_t)NROWS * D_INNER];
__device__ float g_xdbl[(size_t)NROWS * XDBL_W];
__device__ float g_dt  [(size_t)NROWS * D_INNER];
__device__ float g_y   [(size_t)NROWS * D_INNER];
__device__ float g_o   [(size_t)NROWS * D_MODEL];
// tf32-rounded copies of GEMM inputs
__device__ float g_xr [(size_t)NROWS * D_MODEL];
__device__ float g_w1 [(size_t)2 * D_INNER * D_MODEL];
__device__ float g_w3 [(size_t)XDBL_W * D_INNER];
__device__ float g_w4 [(size_t)D_INNER * DT_RANK];
__device__ float g_w6 [(size_t)D_MODEL * D_INNER];

__device__ __forceinline__ unsigned f2tf32(float f) {
    unsigned r;
    asm("cvt.rna.tf32.f32 %0, %1;" : "=r"(r) : "f"(f));
    return r;
}

__device__ __forceinline__ void mma_tf32(float c[4], unsigned a0, unsigned a1,
                                         unsigned a2, unsigned a3,
                                         unsigned b0, unsigned b1) {
    asm volatile(
        "mma.sync.aligned.m16n8k8.row.col.f32.tf32.tf32.f32 "
        "{%0,%1,%2,%3}, {%4,%5,%6,%7}, {%8,%9}, {%0,%1,%2,%3};"
        : "+f"(c[0]), "+f"(c[1]), "+f"(c[2]), "+f"(c[3])
        : "r"(a0), "r"(a1), "r"(a2), "r"(a3), "r"(b0), "r"(b1));
}

#define CP_ASYNC16(dst, src, sz) \
    asm volatile("cp.async.cg.shared.global [%0], [%1], 16, %2;" \
                 :: "r"(dst), "l"(src), "r"(sz) : "memory")
#define CP_COMMIT() asm volatile("cp.async.commit_group;" ::: "memory")
#define CP_WAIT1()  asm volatile("cp.async.wait_group 1;" ::: "memory")

// ================= tf32 tensor-core NT GEMM, cp.async 3-stage =================
// C[m,n] = sum_k A[m,k]*B[n,k].  Inputs pre-rounded to tf32.
// Block tile 128x64, 256 threads = 8 warps (4m x 2n), warp tile 32x32.
// Smem tiles stored in plain gmem order (row-major, 16 words/row).
// k-slot pairing: thread tg feeds slots with k={4tg,4tg+1} (MMA1) and
// {4tg+2,4tg+3} (MMA2) from a single LDS.128; A and B agree per slot, and the
// two MMAs together cover k=0..15 exactly once -> correct k16 accumulation.
// MODE 0: plain   MODE 1: softplus(acc + bias[n])   RND: round output to tf32
template <int MODE, int RND>
__global__ void __launch_bounds__(256)
gemm_tf32(const float* __restrict__ A, const float* __restrict__ Bm,
          float* __restrict__ C, int N, int K,
          int lda, int ldb, int ldc, const float* __restrict__ bias)
{
    __shared__ alignas(16) unsigned As[3][128][16];
    __shared__ alignas(16) unsigned Bs[3][64][16];

    const int tid    = threadIdx.x;
    const int warp   = tid >> 5;
    const int lane   = tid & 31;
    const int g      = lane >> 2;
    const int tg     = lane & 3;
    const int warp_m = warp & 3;
    const int warp_n = warp >> 2;
    const int m0     = blockIdx.y * 128;
    const int n0     = blockIdx.x * 64;

    // loader: A = 512 chunks of 16B (2/thread), B = 256 chunks (1/thread)
    const int chA0 = tid;            // rows 0..63
    const int chA1 = tid + 256;      // rows 64..127
    const int rowA0 = chA0 >> 2, jA0 = chA0 & 3;
    const int rowA1 = chA1 >> 2, jA1 = chA1 & 3;
    const int rowB  = tid >> 2,  jB  = tid & 3;
    const bool bOK  = (n0 + rowB) < N;
    const unsigned szB = bOK ? 16u : 0u;

    const float* srcA0 = A + (size_t)(m0 + rowA0) * lda + 4 * jA0;
    const float* srcA1 = A + (size_t)(m0 + rowA1) * lda + 4 * jA1;
    const float* srcB  = Bm + (size_t)(bOK ? (n0 + rowB) : 0) * ldb + 4 * jB;

    const uint32_t dA0 = (uint32_t)__cvta_generic_to_shared(&As[0][rowA0][4 * jA0]);
    const uint32_t dA1 = (uint32_t)__cvta_generic_to_shared(&As[0][rowA1][4 * jA1]);
    const uint32_t dB  = (uint32_t)__cvta_generic_to_shared(&Bs[0][rowB ][4 * jB ]);
    const uint32_t stA = 128 * 16 * 4;   // bytes per A stage
    const uint32_t stB = 64 * 16 * 4;

    float acc[2][4][4];
#pragma unroll
    for (int i = 0; i < 2; i++)
#pragma unroll
        for (int j = 0; j < 4; j++)
#pragma unroll
            for (int c = 0; c < 4; c++) acc[i][j][c] = 0.f;

    const int nk = K >> 4;

    // prologue: stages 0 and 1
#pragma unroll
    for (int s = 0; s < 2; s++) {
        const int koff = s << 4;
        CP_ASYNC16(dA0 + s * stA, srcA0 + koff, 16u);
        CP_ASYNC16(dA1 + s * stA, srcA1 + koff, 16u);
        CP_ASYNC16(dB  + s * stB, srcB  + koff, szB);
        CP_COMMIT();
    }

    for (int ki = 0; ki < nk; ki++) {
        CP_WAIT1();
        __syncthreads();
        const int buf = ki % 3;

        uint4 afrag[2][2];
#pragma unroll
        for (int i = 0; i < 2; i++) {
            const int r = warp_m * 32 + i * 16 + g;
            afrag[i][0] = *(const uint4*)&As[buf][r    ][4 * tg];
            afrag[i][1] = *(const uint4*)&As[buf][r + 8][4 * tg];
        }
        uint4 bfrag[4];
#pragma unroll
        for (int j = 0; j < 4; j++) {
            const int rn = warp_n * 32 + j * 8 + g;
            bfrag[j] = *(const uint4*)&Bs[buf][rn][4 * tg];
        }

#pragma unroll
        for (int i = 0; i < 2; i++) {
#pragma unroll
            for (int j = 0; j < 4; j++) {
                mma_tf32(acc[i][j], afrag[i][0].x, afrag[i][1].x,
                                    afrag[i][0].y, afrag[i][1].y,
                                    bfrag[j].x, bfrag[j].y);
                mma_tf32(acc[i][j], afrag[i][0].z, afrag[i][1].z,
                                    afrag[i][0].w, afrag[i][1].w,
                                    bfrag[j].z, bfrag[j].w);
            }
        }

        const int kn = ki + 2;
        if (kn < nk) {
            const int s = kn % 3;
            const int koff = kn << 4;
            CP_ASYNC16(dA0 + s * stA, srcA0 + koff, 16u);
            CP_ASYNC16(dA1 + s * stA, srcA1 + koff, 16u);
            CP_ASYNC16(dB  + s * stB, srcB  + koff, szB);
        }
        CP_COMMIT();
    }

    // epilogue
#pragma unroll
    for (int i = 0; i < 2; i++) {
        const int mbase = m0 + warp_m * 32 + i * 16 + g;
#pragma unroll
        for (int j = 0; j < 4; j++) {
            const int nbase = n0 + warp_n * 32 + j * 8 + 2 * tg;
#pragma unroll
            for (int c = 0; c < 4; c++) {
                const int m = mbase + ((c >> 1) << 3);
                const int n = nbase + (c & 1);
                if (n < N) {
                    float v = acc[i][j][c];
                    if (MODE == 1) {
                        v += bias[n];
                        v = (v > 20.f) ? v : log1pf(__expf(v));
                    }
                    if (RND) v = __uint_as_float(f2tf32(v));
                    C[(size_t)m * ldc + n] = v;
                }
            }
        }
    }
}

// ---------------- tf32 pre-round (RNA) ----------------
__global__ void __launch_bounds__(256)
round_tf32_kernel(const float* __restrict__ src, float* __restrict__ dst, int n4)
{
    int i = blockIdx.x * blockDim.x + threadIdx.x;
    if (i < n4) {
        float4 v = ((const float4*)src)[i];
        v.x = __uint_as_float(f2tf32(v.x));
        v.y = __uint_as_float(f2tf32(v.y));
        v.z = __uint_as_float(f2tf32(v.z));
        v.w = __uint_as_float(f2tf32(v.w));
        ((float4*)dst)[i] = v;
    }
}

// ---------------- depthwise causal conv (k=4) + bias + SiLU (+tf32 round) ----------------
__global__ void __launch_bounds__(256)
conv_silu_kernel(const float* __restrict__ conv_w, const float* __restrict__ conv_b)
{
    int idx = blockIdx.x * blockDim.x + threadIdx.x;
    if (idx >= NROWS * D_INNER) return;
    int d = idx & (D_INNER - 1);
    int m = idx >> 11;
    int t = m & (L_SEQ - 1);

    float acc = conv_b[d];
#pragma unroll
    for (int j = 0; j < 4; j++) {
        int tt = t - 3 + j;
        if (tt >= 0)
            acc += g_xz[(size_t)(m - 3 + j) * (2 * D_INNER) + d] * conv_w[d * 4 + j];
    }
    float s = acc / (1.f + __expf(-acc));
    g_uc[(size_t)m * D_INNER + d] = __uint_as_float(f2tf32(s));
}

// ---------------- selective scan (fused +u*D and *silu(z); rounds y) ----------------
__global__ void __launch_bounds__(128)
scan_kernel(const float* __restrict__ A_log, const float* __restrict__ Dw)
{
    const int blk = blockIdx.x;
    const int b   = blk >> 6;
    const int c0  = (blk & 63) * 32;
    const int tid = threadIdx.x;
    const int c   = c0 + (tid >> 2);
    const int g   = tid & 3;

    const float A0 = -__expf(A_log[c * D_STATE + g * 4 + 0]);
    const float A1 = -__expf(A_log[c * D_STATE + g * 4 + 1]);
    const float A2 = -__expf(A_log[c * D_STATE + g * 4 + 2]);
    const float A3 = -__expf(A_log[c * D_STATE + g * 4 + 3]);
    const float Dc = Dw[c];

    float h0 = 0.f, h1 = 0.f, h2 = 0.f, h3 = 0.f;

    const size_t rbase = (size_t)b * L_SEQ;
    const float* dt_p = g_dt   + rbase * D_INNER + c;
    const float* uc_p = g_uc   + rbase * D_INNER + c;
    const float* xd_p = g_xdbl + rbase * XDBL_W;
    const float* z_p  = g_xz   + rbase * (2 * D_INNER) + D_INNER + c;
    float*       y_p  = g_y    + rbase * D_INNER + c;

    for (int t = 0; t < L_SEQ; t++) {
        float  dtv = dt_p[(size_t)t * D_INNER];
        float  uv  = uc_p[(size_t)t * D_INNER];
        float4 Bv  = *(const float4*)(xd_p + (size_t)t * XDBL_W + DT_RANK + g * 4);
        float4 Cv  = *(const float4*)(xd_p + (size_t)t * XDBL_W + DT_RANK + D_STATE + g * 4);

        float du = dtv * uv;
        h0 = h0 * __expf(dtv * A0) + du * Bv.x;
        h1 = h1 * __expf(dtv * A1) + du * Bv.y;
        h2 = h2 * __expf(dtv * A2) + du * Bv.z;
        h3 = h3 * __expf(dtv * A3) + du * Bv.w;

        float p = h0 * Cv.x + h1 * Cv.y + h2 * Cv.z + h3 * Cv.w;
        p += __shfl_xor_sync(0xffffffffu, p, 1);
        p += __shfl_xor_sync(0xffffffffu, p, 2);

        if (g == 0) {
            float zv = z_p[(size_t)t * (2 * D_INNER)];
            float sz = zv / (1.f + __expf(-zv));
            float y  = (p + uv * Dc) * sz;
            y_p[(size_t)t * D_INNER] = __uint_as_float(f2tf32(y));
        }
    }
}

// ---------------- residual + LayerNorm ----------------
__global__ void __launch_bounds__(256)
ln_kernel(const float* __restrict__ x, const float* __restrict__ w,
          const float* __restrict__ b, float* __restrict__ out)
{
    __shared__ float red[8];
    const int m   = blockIdx.x;
    const int tid = threadIdx.x;

    float4 v  = *(const float4*)(g_o + (size_t)m * D_MODEL + tid * 4);
    float4 xr = *(const float4*)(x   + (size_t)m * D_MODEL + tid * 4);
    v.x += xr.x; v.y += xr.y; v.z += xr.z; v.w += xr.w;

    float s = v.x + v.y + v.z + v.w;
#pragma unroll
    for (int o = 16; o; o >>= 1) s += __shfl_xor_sync(0xffffffffu, s, o);
    if ((tid & 31) == 0) red[tid >> 5] = s;
    __syncthreads();
    float tot = 0.f;
#pragma unroll
    for (int i = 0; i < 8; i++) tot += red[i];
    const float mu = tot * (1.f / (float)D_MODEL);
    __syncthreads();

    float d0 = v.x - mu, d1 = v.y - mu, d2 = v.z - mu, d3 = v.w - mu;
    float sq = d0 * d0 + d1 * d1 + d2 * d2 + d3 * d3;
#pragma unroll
    for (int o = 16; o; o >>= 1) sq += __shfl_xor_sync(0xffffffffu, sq, o);
    if ((tid & 31) == 0) red[tid >> 5] = sq;
    __syncthreads();
    float tot2 = 0.f;
#pragma unroll
    for (int i = 0; i < 8; i++) tot2 += red[i];
    const float rs = rsqrtf(tot2 * (1.f / (float)D_MODEL) + 1e-5f);

    float4 wv = *(const float4*)(w + tid * 4);
    float4 bv = *(const float4*)(b + tid * 4);
    float4 o4;
    o4.x = d0 * rs * wv.x + bv.x;
    o4.y = d1 * rs * wv.y + bv.y;
    o4.z = d2 * rs * wv.z + bv.z;
    o4.w = d3 * rs * wv.w + bv.w;
    *(float4*)(out + (size_t)m * D_MODEL + tid * 4) = o4;
}

// ---------------- launch ----------------
extern "C" void kernel_launch(void* const* d_in, const int* in_sizes, int n_in,
                              void* d_out, int out_size)
{
    const float* x          = (const float*)d_in[0];
    const float* in_proj_w  = (const float*)d_in[1];
    const float* conv_w     = (const float*)d_in[2];
    const float* conv_b     = (const float*)d_in[3];
    const float* x_proj_w   = (const float*)d_in[4];
    const float* dt_proj_w  = (const float*)d_in[5];
    const float* dt_proj_b  = (const float*)d_in[6];
    const float* A_log      = (const float*)d_in[7];
    const float* Dw         = (const float*)d_in[8];
    const float* out_proj_w = (const float*)d_in[9];
    const float* ln_w       = (const float*)d_in[10];
    const float* ln_b       = (const float*)d_in[11];
    float* out = (float*)d_out;

    float *p_xz, *p_uc, *p_xdbl, *p_dt, *p_y, *p_o;
    float *p_xr, *p_w1, *p_w3, *p_w4, *p_w6;
    cudaGetSymbolAddress((void**)&p_xz,   g_xz);
    cudaGetSymbolAddress((void**)&p_uc,   g_uc);
    cudaGetSymbolAddress((void**)&p_xdbl, g_xdbl);
    cudaGetSymbolAddress((void**)&p_dt,   g_dt);
    cudaGetSymbolAddress((void**)&p_y,    g_y);
    cudaGetSymbolAddress((void**)&p_o,    g_o);
    cudaGetSymbolAddress((void**)&p_xr,   g_xr);
    cudaGetSymbolAddress((void**)&p_w1,   g_w1);
    cudaGetSymbolAddress((void**)&p_w3,   g_w3);
    cudaGetSymbolAddress((void**)&p_w4,   g_w4);
    cudaGetSymbolAddress((void**)&p_w6,   g_w6);

    // pre-rounds (ordered so gemm1 is launch index 3 -> ncu captures it)
    round_tf32_kernel<<<(NROWS * D_MODEL / 4 + 255) / 256, 256>>>(x,          p_xr, NROWS * D_MODEL / 4);
    round_tf32_kernel<<<(2*D_INNER*D_MODEL/4 + 255) / 256, 256>>>(in_proj_w,  p_w1, 2*D_INNER*D_MODEL/4);
    round_tf32_kernel<<<(XDBL_W*D_INNER/4   + 255) / 256, 256>>>(x_proj_w,   p_w3, XDBL_W*D_INNER/4);

    // 1) xz = x @ in_proj_w.T  (4096 x 4096, K=1024)   [launch index 3]
    gemm_tf32<0, 0><<<dim3(4096 / 64, 4096 / 128), 256>>>(
        p_xr, p_w1, p_xz, 2 * D_INNER, D_MODEL, D_MODEL, D_MODEL, 2 * D_INNER, nullptr);

    round_tf32_kernel<<<(D_INNER*DT_RANK/4  + 255) / 256, 256>>>(dt_proj_w,  p_w4, D_INNER*DT_RANK/4);
    round_tf32_kernel<<<(D_MODEL*D_INNER/4  + 255) / 256, 256>>>(out_proj_w, p_w6, D_MODEL*D_INNER/4);

    // 2) u_c = silu(depthwise_conv(u) + b)   (rounded)
    conv_silu_kernel<<<(NROWS * D_INNER) / 256, 256>>>(conv_w, conv_b);

    // 3) x_dbl = u_c @ x_proj_w.T  (4096 x 96, K=2048, rounded output)
    gemm_tf32<0, 1><<<dim3(2, 4096 / 128), 256>>>(
        p_uc, p_w3, p_xdbl, XDBL_W, D_INNER, D_INNER, D_INNER, XDBL_W, nullptr);

    // 4) dt = softplus(dt_lr @ dt_proj_w.T + b)  (4096 x 2048, K=64, lda=96)
    gemm_tf32<1, 0><<<dim3(D_INNER / 64, 4096 / 128), 256>>>(
        p_xdbl, p_w4, p_dt, D_INNER, DT_RANK, XDBL_W, DT_RANK, D_INNER, dt_proj_b);

    // 5) selective scan (rounds y)
    scan_kernel<<<128, 128>>>(A_log, Dw);

    // 6) o = y @ out_proj_w.T  (4096 x 1024, K=2048)
    gemm_tf32<0, 0><<<dim3(D_MODEL / 64, 4096 / 128), 256>>>(
        p_y, p_w6, p_o, D_MODEL, D_INNER, D_INNER, D_INNER, D_MODEL, nullptr);

    // 7) out = LayerNorm(o + x)
    ln_kernel<<<NROWS, 256>>>(x, ln_w, ln_b, out);
}

// round 7
// speedup vs baseline: 3.3569x; 2.8075x over previous
#include <cuda_runtime.h>
#include <math.h>
#include <stdint.h>

#define B_SZ     2
#define L_SEQ    2048
#define D_MODEL  1024
#define D_INNER  2048
#define D_STATE  16
#define DT_RANK  64
#define NROWS    (B_SZ * L_SEQ)          // 4096
#define XDBL_W   (DT_RANK + 2 * D_STATE) // 96
#define SCAN_T   64
#define NCHUNK   (L_SEQ / SCAN_T)

// ---------------- scratch (device globals; no allocs allowed) ----------------
__device__ float g_xz  [(size_t)NROWS * 2 * D_INNER];
__device__ float g_uc  [(size_t)NROWS * D_INNER];
__device__ float g_xdbl[(size_t)NROWS * XDBL_W];
__device__ float g_dt  [(size_t)NROWS * D_INNER];
__device__ float g_y   [(size_t)NROWS * D_INNER];
__device__ float g_o   [(size_t)NROWS * D_MODEL];
// tf32-rounded copies of GEMM inputs
__device__ float g_xr [(size_t)NROWS * D_MODEL];
__device__ float g_w1 [(size_t)2 * D_INNER * D_MODEL];
__device__ float g_w3 [(size_t)XDBL_W * D_INNER];
__device__ float g_w4 [(size_t)D_INNER * DT_RANK];
__device__ float g_w6 [(size_t)D_MODEL * D_INNER];

__device__ __forceinline__ unsigned f2tf32(float f) {
    unsigned r;
    asm("cvt.rna.tf32.f32 %0, %1;" : "=r"(r) : "f"(f));
    return r;
}

__device__ __forceinline__ void mma_tf32(float c[4], unsigned a0, unsigned a1,
                                         unsigned a2, unsigned a3,
                                         unsigned b0, unsigned b1) {
    asm volatile(
        "mma.sync.aligned.m16n8k8.row.col.f32.tf32.tf32.f32 "
        "{%0,%1,%2,%3}, {%4,%5,%6,%7}, {%8,%9}, {%0,%1,%2,%3};"
        : "+f"(c[0]), "+f"(c[1]), "+f"(c[2]), "+f"(c[3])
        : "r"(a0), "r"(a1), "r"(a2), "r"(a3), "r"(b0), "r"(b1));
}

#define CP_ASYNC16(dst, src, sz) \
    asm volatile("cp.async.cg.shared.global [%0], [%1], 16, %2;" \
                 :: "r"(dst), "l"(src), "r"(sz) : "memory")
#define CP_A16(dst, src) \
    asm volatile("cp.async.cg.shared.global [%0], [%1], 16;" \
                 :: "r"(dst), "l"(src) : "memory")
#define CP_COMMIT() asm volatile("cp.async.commit_group;" ::: "memory")
#define CP_WAIT1()  asm volatile("cp.async.wait_group 1;" ::: "memory")
#define CP_WAIT0()  asm volatile("cp.async.wait_group 0;" ::: "memory")

// ================= tf32 tensor-core NT GEMM, cp.async 3-stage =================
// (unchanged from round 5 — verified correct+fast enough for now)
template <int MODE, int RND>
__global__ void __launch_bounds__(256)
gemm_tf32(const float* __restrict__ A, const float* __restrict__ Bm,
          float* __restrict__ C, int N, int K,
          int lda, int ldb, int ldc, const float* __restrict__ bias)
{
    __shared__ alignas(16) unsigned As[3][128][16];
    __shared__ alignas(16) unsigned Bs[3][64][16];

    const int tid    = threadIdx.x;
    const int warp   = tid >> 5;
    const int lane   = tid & 31;
    const int g      = lane >> 2;
    const int tg     = lane & 3;
    const int warp_m = warp & 3;
    const int warp_n = warp >> 2;
    const int m0     = blockIdx.y * 128;
    const int n0     = blockIdx.x * 64;

    const int chA0 = tid;
    const int chA1 = tid + 256;
    const int rowA0 = chA0 >> 2, jA0 = chA0 & 3;
    const int rowA1 = chA1 >> 2, jA1 = chA1 & 3;
    const int rowB  = tid >> 2,  jB  = tid & 3;
    const bool bOK  = (n0 + rowB) < N;
    const unsigned szB = bOK ? 16u : 0u;

    const float* srcA0 = A + (size_t)(m0 + rowA0) * lda + 4 * jA0;
    const float* srcA1 = A + (size_t)(m0 + rowA1) * lda + 4 * jA1;
    const float* srcB  = Bm + (size_t)(bOK ? (n0 + rowB) : 0) * ldb + 4 * jB;

    const uint32_t dA0 = (uint32_t)__cvta_generic_to_shared(&As[0][rowA0][4 * jA0]);
    const uint32_t dA1 = (uint32_t)__cvta_generic_to_shared(&As[0][rowA1][4 * jA1]);
    const uint32_t dB  = (uint32_t)__cvta_generic_to_shared(&Bs[0][rowB ][4 * jB ]);
    const uint32_t stA = 128 * 16 * 4;
    const uint32_t stB = 64 * 16 * 4;

    float acc[2][4][4];
#pragma unroll
    for (int i = 0; i < 2; i++)
#pragma unroll
        for (int j = 0; j < 4; j++)
#pragma unroll
            for (int c = 0; c < 4; c++) acc[i][j][c] = 0.f;

    const int nk = K >> 4;

#pragma unroll
    for (int s = 0; s < 2; s++) {
        const int koff = s << 4;
        CP_ASYNC16(dA0 + s * stA, srcA0 + koff, 16u);
        CP_ASYNC16(dA1 + s * stA, srcA1 + koff, 16u);
        CP_ASYNC16(dB  + s * stB, srcB  + koff, szB);
        CP_COMMIT();
    }

    for (int ki = 0; ki < nk; ki++) {
        CP_WAIT1();
        __syncthreads();
        const int buf = ki % 3;

        uint4 afrag[2][2];
#pragma unroll
        for (int i = 0; i < 2; i++) {
            const int r = warp_m * 32 + i * 16 + g;
            afrag[i][0] = *(const uint4*)&As[buf][r    ][4 * tg];
            afrag[i][1] = *(const uint4*)&As[buf][r + 8][4 * tg];
        }
        uint4 bfrag[4];
#pragma unroll
        for (int j = 0; j < 4; j++) {
            const int rn = warp_n * 32 + j * 8 + g;
            bfrag[j] = *(const uint4*)&Bs[buf][rn][4 * tg];
        }

#pragma unroll
        for (int i = 0; i < 2; i++) {
#pragma unroll
            for (int j = 0; j < 4; j++) {
                mma_tf32(acc[i][j], afrag[i][0].x, afrag[i][1].x,
                                    afrag[i][0].y, afrag[i][1].y,
                                    bfrag[j].x, bfrag[j].y);
                mma_tf32(acc[i][j], afrag[i][0].z, afrag[i][1].z,
                                    afrag[i][0].w, afrag[i][1].w,
                                    bfrag[j].z, bfrag[j].w);
            }
        }

        const int kn = ki + 2;
        if (kn < nk) {
            const int s = kn % 3;
            const int koff = kn << 4;
            CP_ASYNC16(dA0 + s * stA, srcA0 + koff, 16u);
            CP_ASYNC16(dA1 + s * stA, srcA1 + koff, 16u);
            CP_ASYNC16(dB  + s * stB, srcB  + koff, szB);
        }
        CP_COMMIT();
    }

#pragma unroll
    for (int i = 0; i < 2; i++) {
        const int mbase = m0 + warp_m * 32 + i * 16 + g;
#pragma unroll
        for (int j = 0; j < 4; j++) {
            const int nbase = n0 + warp_n * 32 + j * 8 + 2 * tg;
#pragma unroll
            for (int c = 0; c < 4; c++) {
                const int m = mbase + ((c >> 1) << 3);
                const int n = nbase + (c & 1);
                if (n < N) {
                    float v = acc[i][j][c];
                    if (MODE == 1) {
                        v += bias[n];
                        v = (v > 20.f) ? v : log1pf(__expf(v));
                    }
                    if (RND) v = __uint_as_float(f2tf32(v));
                    C[(size_t)m * ldc + n] = v;
                }
            }
        }
    }
}

// ---------------- tf32 pre-round (RNA) ----------------
__global__ void __launch_bounds__(256)
round_tf32_kernel(const float* __restrict__ src, float* __restrict__ dst, int n4)
{
    int i = blockIdx.x * blockDim.x + threadIdx.x;
    if (i < n4) {
        float4 v = ((const float4*)src)[i];
        v.x = __uint_as_float(f2tf32(v.x));
        v.y = __uint_as_float(f2tf32(v.y));
        v.z = __uint_as_float(f2tf32(v.z));
        v.w = __uint_as_float(f2tf32(v.w));
        ((float4*)dst)[i] = v;
    }
}

// ---------------- depthwise causal conv (k=4) + bias + SiLU (+tf32 round) ----------------
__global__ void __launch_bounds__(256)
conv_silu_kernel(const float* __restrict__ conv_w, const float* __restrict__ conv_b)
{
    int idx = blockIdx.x * blockDim.x + threadIdx.x;
    if (idx >= NROWS * D_INNER) return;
    int d = idx & (D_INNER - 1);
    int m = idx >> 11;
    int t = m & (L_SEQ - 1);

    float acc = conv_b[d];
#pragma unroll
    for (int j = 0; j < 4; j++) {
        int tt = t - 3 + j;
        if (tt >= 0)
            acc += g_xz[(size_t)(m - 3 + j) * (2 * D_INNER) + d] * conv_w[d * 4 + j];
    }
    float s = acc / (1.f + __expf(-acc));
    g_uc[(size_t)m * D_INNER + d] = __uint_as_float(f2tf32(s));
}

// ---------------- selective scan: cp.async-staged, chunked double buffer ------
// 128 blocks x 128 threads; block handles (batch b, 32 channels).
// Per chunk of SCAN_T=64 steps, stage 4 tiles (dt, u, z, B|C) of 64x128B each
// into smem (all rows coalesced), double buffered; inner loop is smem-only.
__global__ void __launch_bounds__(128)
scan_kernel(const float* __restrict__ A_log, const float* __restrict__ Dw)
{
    extern __shared__ float sm[];
    // layout (floats): dt[2][2048] | uc[2][2048] | z[2][2048] | bc[2][2048]
    float* s_dt = sm;
    float* s_uc = sm + 4096;
    float* s_z  = sm + 8192;
    float* s_bc = sm + 12288;

    const int blk = blockIdx.x;
    const int b   = blk >> 6;
    const int c0  = (blk & 63) * 32;
    const int tid = threadIdx.x;
    const int cl  = tid >> 2;          // channel-local 0..31
    const int g   = tid & 3;           // state group
    const int c   = c0 + cl;

    const float A0 = -__expf(A_log[c * D_STATE + g * 4 + 0]);
    const float A1 = -__expf(A_log[c * D_STATE + g * 4 + 1]);
    const float A2 = -__expf(A_log[c * D_STATE + g * 4 + 2]);
    const float A3 = -__expf(A_log[c * D_STATE + g * 4 + 3]);
    const float Dc = Dw[c];

    const size_t rbase = (size_t)b * L_SEQ;
    const char* dt_g = (const char*)(g_dt   + rbase * D_INNER + c0);
    const char* uc_g = (const char*)(g_uc   + rbase * D_INNER + c0);
    const char* z_g  = (const char*)(g_xz   + rbase * (2 * D_INNER) + D_INNER + c0);
    const char* bc_g = (const char*)(g_xdbl + rbase * XDBL_W + DT_RANK);
    float*      y_p  = g_y + rbase * D_INNER + c;

    const uint32_t smem0 = (uint32_t)__cvta_generic_to_shared(sm);
    const uint32_t o_dt = 0, o_uc = 16384, o_z = 32768, o_bc = 49152;
    const uint32_t bufB = SCAN_T * 32 * 4;   // 8192 bytes per buffer

    // loader: per tile 512 x 16B pieces; 128 threads -> 4 pieces/thread/tile
    auto stage = [&](int chunk, int buf) {
        const size_t t0 = (size_t)chunk * SCAN_T;
        const uint32_t bo = (uint32_t)buf * bufB;
#pragma unroll
        for (int i = 0; i < 4; i++) {
            const int p = tid + i * 128;
            const int row = p >> 3, seg = p & 7;
            const uint32_t dofs = bo + row * 128 + seg * 16;
            const size_t tr = t0 + row;
            CP_A16(smem0 + o_dt + dofs, dt_g + tr * 8192  + seg * 16);
            CP_A16(smem0 + o_uc + dofs, uc_g + tr * 8192  + seg * 16);
            CP_A16(smem0 + o_z  + dofs, z_g  + tr * 16384 + seg * 16);
            CP_A16(smem0 + o_bc + dofs, bc_g + tr * 384   + seg * 16);
        }
        CP_COMMIT();
    };

    float h0 = 0.f, h1 = 0.f, h2 = 0.f, h3 = 0.f;

    stage(0, 0);
    for (int k = 0; k < NCHUNK; k++) {
        const int buf = k & 1;
        if (k + 1 < NCHUNK) { stage(k + 1, buf ^ 1); CP_WAIT1(); }
        else                { CP_WAIT0(); }
        __syncthreads();

        const int tb = buf * 2048;
        float* yrow = y_p + (size_t)k * SCAN_T * D_INNER;

#pragma unroll 4
        for (int t = 0; t < SCAN_T; t++) {
            const int r = tb + t * 32;
            const float dtv = s_dt[r + cl];
            const float uv  = s_uc[r + cl];
            const float4 Bv = *(const float4*)&s_bc[r + g * 4];
            const float4 Cv = *(const float4*)&s_bc[r + 16 + g * 4];

            const float du = dtv * uv;
            h0 = h0 * __expf(dtv * A0) + du * Bv.x;
            h1 = h1 * __expf(dtv * A1) + du * Bv.y;
            h2 = h2 * __expf(dtv * A2) + du * Bv.z;
            h3 = h3 * __expf(dtv * A3) + du * Bv.w;

            float p = h0 * Cv.x + h1 * Cv.y + h2 * Cv.z + h3 * Cv.w;
            p += __shfl_xor_sync(0xffffffffu, p, 1);
            p += __shfl_xor_sync(0xffffffffu, p, 2);

            if (g == 0) {
                const float zv = s_z[r + cl];
                const float sz = zv / (1.f + __expf(-zv));
                const float y  = (p + uv * Dc) * sz;
                yrow[(size_t)t * D_INNER] = __uint_as_float(f2tf32(y));
            }
        }
        __syncthreads();
    }
}

// ---------------- residual + LayerNorm ----------------
__global__ void __launch_bounds__(256)
ln_kernel(const float* __restrict__ x, const float* __restrict__ w,
          const float* __restrict__ b, float* __restrict__ out)
{
    __shared__ float red[8];
    const int m   = blockIdx.x;
    const int tid = threadIdx.x;

    float4 v  = *(const float4*)(g_o + (size_t)m * D_MODEL + tid * 4);
    float4 xr = *(const float4*)(x   + (size_t)m * D_MODEL + tid * 4);
    v.x += xr.x; v.y += xr.y; v.z += xr.z; v.w += xr.w;

    float s = v.x + v.y + v.z + v.w;
#pragma unroll
    for (int o = 16; o; o >>= 1) s += __shfl_xor_sync(0xffffffffu, s, o);
    if ((tid & 31) == 0) red[tid >> 5] = s;
    __syncthreads();
    float tot = 0.f;
#pragma unroll
    for (int i = 0; i < 8; i++) tot += red[i];
    const float mu = tot * (1.f / (float)D_MODEL);
    __syncthreads();

    float d0 = v.x - mu, d1 = v.y - mu, d2 = v.z - mu, d3 = v.w - mu;
    float sq = d0 * d0 + d1 * d1 + d2 * d2 + d3 * d3;
#pragma unroll
    for (int o = 16; o; o >>= 1) sq += __shfl_xor_sync(0xffffffffu, sq, o);
    if ((tid & 31) == 0) red[tid >> 5] = sq;
    __syncthreads();
    float tot2 = 0.f;
#pragma unroll
    for (int i = 0; i < 8; i++) tot2 += red[i];
    const float rs = rsqrtf(tot2 * (1.f / (float)D_MODEL) + 1e-5f);

    float4 wv = *(const float4*)(w + tid * 4);
    float4 bv = *(const float4*)(b + tid * 4);
    float4 o4;
    o4.x = d0 * rs * wv.x + bv.x;
    o4.y = d1 * rs * wv.y + bv.y;
    o4.z = d2 * rs * wv.z + bv.z;
    o4.w = d3 * rs * wv.w + bv.w;
    *(float4*)(out + (size_t)m * D_MODEL + tid * 4) = o4;
}

// ---------------- launch ----------------
extern "C" void kernel_launch(void* const* d_in, const int* in_sizes, int n_in,
                              void* d_out, int out_size)
{
    const float* x          = (const float*)d_in[0];
    const float* in_proj_w  = (const float*)d_in[1];
    const float* conv_w     = (const float*)d_in[2];
    const float* conv_b     = (const float*)d_in[3];
    const float* x_proj_w   = (const float*)d_in[4];
    const float* dt_proj_w  = (const float*)d_in[5];
    const float* dt_proj_b  = (const float*)d_in[6];
    const float* A_log      = (const float*)d_in[7];
    const float* Dw         = (const float*)d_in[8];
    const float* out_proj_w = (const float*)d_in[9];
    const float* ln_w       = (const float*)d_in[10];
    const float* ln_b       = (const float*)d_in[11];
    float* out = (float*)d_out;

    float *p_xz, *p_uc, *p_xdbl, *p_dt, *p_y, *p_o;
    float *p_xr, *p_w1, *p_w3, *p_w4, *p_w6;
    cudaGetSymbolAddress((void**)&p_xz,   g_xz);
    cudaGetSymbolAddress((void**)&p_uc,   g_uc);
    cudaGetSymbolAddress((void**)&p_xdbl, g_xdbl);
    cudaGetSymbolAddress((void**)&p_dt,   g_dt);
    cudaGetSymbolAddress((void**)&p_y,    g_y);
    cudaGetSymbolAddress((void**)&p_o,    g_o);
    cudaGetSymbolAddress((void**)&p_xr,   g_xr);
    cudaGetSymbolAddress((void**)&p_w1,   g_w1);
    cudaGetSymbolAddress((void**)&p_w3,   g_w3);
    cudaGetSymbolAddress((void**)&p_w4,   g_w4);
    cudaGetSymbolAddress((void**)&p_w6,   g_w6);

    cudaFuncSetAttribute(scan_kernel, cudaFuncAttributeMaxDynamicSharedMemorySize, 65536);

    // pre-rounds (gemm1 stays at launch index 3 for ncu tracking)
    round_tf32_kernel<<<(NROWS * D_MODEL / 4 + 255) / 256, 256>>>(x,          p_xr, NROWS * D_MODEL / 4);
    round_tf32_kernel<<<(2*D_INNER*D_MODEL/4 + 255) / 256, 256>>>(in_proj_w,  p_w1, 2*D_INNER*D_MODEL/4);
    round_tf32_kernel<<<(XDBL_W*D_INNER/4   + 255) / 256, 256>>>(x_proj_w,   p_w3, XDBL_W*D_INNER/4);

    // 1) xz = x @ in_proj_w.T  (4096 x 4096, K=1024)
    gemm_tf32<0, 0><<<dim3(4096 / 64, 4096 / 128), 256>>>(
        p_xr, p_w1, p_xz, 2 * D_INNER, D_MODEL, D_MODEL, D_MODEL, 2 * D_INNER, nullptr);

    round_tf32_kernel<<<(D_INNER*DT_RANK/4  + 255) / 256, 256>>>(dt_proj_w,  p_w4, D_INNER*DT_RANK/4);
    round_tf32_kernel<<<(D_MODEL*D_INNER/4  + 255) / 256, 256>>>(out_proj_w, p_w6, D_MODEL*D_INNER/4);

    // 2) u_c = silu(depthwise_conv(u) + b)   (rounded)
    conv_silu_kernel<<<(NROWS * D_INNER) / 256, 256>>>(conv_w, conv_b);

    // 3) x_dbl = u_c @ x_proj_w.T  (4096 x 96, K=2048, rounded output)
    gemm_tf32<0, 1><<<dim3(2, 4096 / 128), 256>>>(
        p_uc, p_w3, p_xdbl, XDBL_W, D_INNER, D_INNER, D_INNER, XDBL_W, nullptr);

    // 4) dt = softplus(dt_lr @ dt_proj_w.T + b)  (4096 x 2048, K=64, lda=96)
    gemm_tf32<1, 0><<<dim3(D_INNER / 64, 4096 / 128), 256>>>(
        p_xdbl, p_w4, p_dt, D_INNER, DT_RANK, XDBL_W, DT_RANK, D_INNER, dt_proj_b);

    // 5) selective scan (cp.async staged, rounds y)
    scan_kernel<<<128, 128, 65536>>>(A_log, Dw);

    // 6) o = y @ out_proj_w.T  (4096 x 1024, K=2048)
    gemm_tf32<0, 0><<<dim3(D_MODEL / 64, 4096 / 128), 256>>>(
        p_y, p_w6, p_o, D_MODEL, D_INNER, D_INNER, D_INNER, D_MODEL, nullptr);

    // 7) out = LayerNorm(o + x)
    ln_kernel<<<NROWS, 256>>>(x, ln_w, ln_b, out);
}